// round 8
// baseline (speedup 1.0000x reference)
#include <cuda_runtime.h>

#define PNUM    1024
#define BNUM    8
#define NB      11
#define NBINS   1331
#define IPB     2              // i-rows per block = 1 packed f32x2 unit
#define THREADS 256
#define JSTEPS  (PNUM/THREADS) // 4

typedef unsigned long long u64f2;   // two packed fp32

__device__ int g_hist[BNUM * NBINS];

// ---- packed f32x2 primitives (sm_100+) ----
__device__ __forceinline__ u64f2 pk2(float lo, float hi) {
    u64f2 r; asm("mov.b64 %0, {%1, %2};" : "=l"(r) : "f"(lo), "f"(hi)); return r;
}
__device__ __forceinline__ void up2(u64f2 v, float& lo, float& hi) {
    asm("mov.b64 {%0, %1}, %2;" : "=f"(lo), "=f"(hi) : "l"(v));
}
__device__ __forceinline__ u64f2 f2fma(u64f2 a, u64f2 b, u64f2 c) {
    u64f2 d; asm("fma.rn.f32x2 %0, %1, %2, %3;" : "=l"(d) : "l"(a), "l"(b), "l"(c)); return d;
}
__device__ __forceinline__ u64f2 f2mul(u64f2 a, u64f2 b) {
    u64f2 d; asm("mul.rn.f32x2 %0, %1, %2;" : "=l"(d) : "l"(a), "l"(b)); return d;
}
__device__ __forceinline__ u64f2 f2add(u64f2 a, u64f2 b) {
    u64f2 d; asm("add.rn.f32x2 %0, %1, %2;" : "=l"(d) : "l"(a), "l"(b)); return d;
}
__device__ __forceinline__ u64f2 rsq2(u64f2 v) {   // per-lane rsqrt (MUFU is scalar)
    float a, b; up2(v, a, b);
    return pk2(rsqrtf(a), rsqrtf(b));
}

// Scalar tail: atan2 fixups + binning + histogram add (one pack lane).
__device__ __forceinline__ void epilogue(float af, float pf, float r, float y,
                                         bool aygt, bool xneg, int i, int j,
                                         int* __restrict__ hist) {
    if (aygt) r = 1.57079637f - r;
    if (xneg) r = 3.14159274f - r;
    float tf = fmaf(r, copysignf(1.75070429f, y), 5.5f);  // (r/pi)*5.5+5.5, sign of y
    int ai = min((int)af, NB - 1);
    int pb = min((int)pf, NB - 1);
    int ti = min((int)tf, NB - 1);
    int idx = (ai * NB + pb) * NB + ti;
    if (idx < 0) idx += NBINS;               // JAX: single negative wrap
    if ((unsigned)idx < (unsigned)NBINS && j != i)
        atomicAdd(&hist[idx], 1);
}

__global__ __launch_bounds__(THREADS, 4) void fpfh_accum_kernel(const float* __restrict__ x) {
    __shared__ int s_hist[NBINS];

    const int b  = blockIdx.y;
    const int i0 = blockIdx.x * IPB;   // this block's 2 i-points (packed lo/hi)

    for (int t = threadIdx.x; t < NBINS; t += THREADS) s_hist[t] = 0;

    const float* __restrict__ base = x + (size_t)b * PNUM * 6;

    // i-pair constants: lo lane = i0, hi lane = i0+1
    const float* p0 = base + (size_t)i0 * 6;
    const float* p1 = base + (size_t)(i0 + 1) * 6;
    const float p0x = __ldg(p0 + 0), p0y = __ldg(p0 + 1), p0z = __ldg(p0 + 2);
    const float n0x = __ldg(p0 + 3), n0y = __ldg(p0 + 4), n0z = __ldg(p0 + 5);
    const float p1x = __ldg(p1 + 0), p1y = __ldg(p1 + 1), p1z = __ldg(p1 + 2);
    const float n1x = __ldg(p1 + 3), n1y = __ldg(p1 + 4), n1z = __ldg(p1 + 5);
    const u64f2 NPX = pk2(-p0x, -p1x), NPY = pk2(-p0y, -p1y), NPZ = pk2(-p0z, -p1z);
    const u64f2 NX  = pk2( n0x,  n1x), NY  = pk2( n0y,  n1y), NZ  = pk2( n0z,  n1z);
    const u64f2 MNX = pk2(-n0x, -n1x), MNY = pk2(-n0y, -n1y), MNZ = pk2(-n0z, -n1z);
    __syncthreads();

    // packed atan polynomial constants
    const u64f2 CA1  = pk2( 0.99997726f,  0.99997726f);
    const u64f2 CA3  = pk2(-0.33262347f, -0.33262347f);
    const u64f2 CA5  = pk2( 0.19354346f,  0.19354346f);
    const u64f2 CA7  = pk2(-0.11643287f, -0.11643287f);
    const u64f2 CA9  = pk2( 0.05265332f,  0.05265332f);
    const u64f2 CA11 = pk2(-0.01172120f, -0.01172120f);
    const u64f2 K55  = pk2( 5.5f, 5.5f);

    #pragma unroll
    for (int jj = 0; jj < JSTEPS; jj++) {
        const int j = threadIdx.x + jj * THREADS;
        const float2* __restrict__ pj = (const float2*)(base + (size_t)j * 6);
        const float2 q0 = __ldg(pj + 0);
        const float2 q1 = __ldg(pj + 1);
        const float2 q2 = __ldg(pj + 2);
        const u64f2 JX  = pk2(q0.x, q0.x), JY  = pk2(q0.y, q0.y), JZ  = pk2(q1.x, q1.x);
        const u64f2 JNX = pk2(q1.y, q1.y), JNY = pk2(q2.x, q2.x), JNZ = pk2(q2.y, q2.y);

        // delta = pos_j - pos_i  (both i's at once)
        const u64f2 dx = f2add(JX, NPX);
        const u64f2 dy = f2add(JY, NPY);
        const u64f2 dz = f2add(JZ, NPZ);

        const u64f2 d2   = f2fma(dx, dx, f2fma(dy, dy, f2mul(dz, dz)));
        const u64f2 pdot = f2fma(NX, dx, f2fma(NY, dy, f2mul(NZ, dz)));
        const u64f2 phi2 = f2mul(pdot, rsq2(d2));

        // v = cross(delta, ni)
        const u64f2 vx = f2fma(dy, NZ, f2mul(dz, MNY));
        const u64f2 vy = f2fma(dz, NX, f2mul(dx, MNZ));
        const u64f2 vz = f2fma(dx, NY, f2mul(dy, MNX));
        const u64f2 v2 = f2fma(vx, vx, f2fma(vy, vy, f2mul(vz, vz)));
        const u64f2 adot = f2fma(vx, JNX, f2fma(vy, JNY, f2mul(vz, JNZ)));
        const u64f2 alpha2 = f2mul(adot, rsq2(v2));

        // w = cross(ni, v)
        const u64f2 wx = f2fma(NY, vz, f2mul(MNZ, vy));
        const u64f2 wy = f2fma(NZ, vx, f2mul(MNX, vz));
        const u64f2 wz = f2fma(NX, vy, f2mul(MNY, vx));
        const u64f2 w2   = f2fma(wx, wx, f2fma(wy, wy, f2mul(wz, wz)));
        const u64f2 wdot = f2fma(wx, JNX, f2fma(wy, JNY, f2mul(wz, JNZ)));
        const u64f2 ndot = f2fma(NX, JNX, f2fma(NY, JNY, f2mul(NZ, JNZ)));

        // theta = atan2(wdot, ndot*|w|)  [scale-folded form]
        float w2a, w2b; up2(w2, w2a, w2b);
        float ya,  yb;  up2(wdot, ya, yb);
        float na,  nb;  up2(ndot, na, nb);
        const float xa = na * (w2a * rsqrtf(w2a));
        const float xb = nb * (w2b * rsqrtf(w2b));

        const float axa = fabsf(xa), aya = fabsf(ya);
        const float axb = fabsf(xb), ayb = fabsf(yb);
        const bool  ga = aya > axa, gb = ayb > axb;
        const bool  sa = xa < 0.0f, sb = xb < 0.0f;
        const float ta = __fdividef(fminf(axa, aya), fmaxf(axa, aya));
        const float tb = __fdividef(fminf(axb, ayb), fmaxf(axb, ayb));

        const u64f2 T  = pk2(ta, tb);
        const u64f2 T2 = f2mul(T, T);
        u64f2 P = f2fma(T2, CA11, CA9);
        P = f2fma(T2, P, CA7);
        P = f2fma(T2, P, CA5);
        P = f2fma(T2, P, CA3);
        P = f2fma(T2, P, CA1);
        const u64f2 R = f2mul(P, T);
        float ra, rb; up2(R, ra, rb);

        const u64f2 AF = f2fma(alpha2, K55, K55);
        const u64f2 PF = f2fma(phi2,  K55, K55);
        float afa, afb; up2(AF, afa, afb);
        float pfa, pfb; up2(PF, pfa, pfb);

        epilogue(afa, pfa, ra, ya, ga, sa, i0,     j, s_hist);
        epilogue(afb, pfb, rb, yb, gb, sb, i0 + 1, j, s_hist);
    }
    __syncthreads();

    // Flush block-private histogram to the per-batch global histogram.
    int* __restrict__ gh = &g_hist[b * NBINS];
    for (int t = threadIdx.x; t < NBINS; t += THREADS) {
        int c = s_hist[t];
        if (c) atomicAdd(&gh[t], c);
    }
}

__global__ void fpfh_finalize_kernel(float* __restrict__ out) {
    int t = blockIdx.x * blockDim.x + threadIdx.x;
    if (t < BNUM * NBINS) {
        out[t] = (float)g_hist[t] / 1047552.0f;  // / (1024*1023)
        g_hist[t] = 0;                           // reset for next graph replay
    }
}

// No-op: steers ncu's fixed launch-skip so the accum kernel gets profiled.
__global__ void fpfh_pad_kernel() {}

extern "C" void kernel_launch(void* const* d_in, const int* in_sizes, int n_in,
                              void* d_out, int out_size) {
    const float* x = (const float*)d_in[0];
    float* out = (float*)d_out;

    dim3 grid(PNUM / IPB, BNUM);   // 512 x 8 = 4096 blocks
    fpfh_accum_kernel<<<grid, THREADS>>>(x);

    int total = BNUM * NBINS;
    fpfh_finalize_kernel<<<(total + 255) / 256, 256>>>(out);

    fpfh_pad_kernel<<<1, 32>>>();
}

// round 9
// speedup vs baseline: 1.1705x; 1.1705x over previous
#include <cuda_runtime.h>

#define PNUM    1024
#define BNUM    8
#define NB      11
#define NBINS   1331
#define IPB     4              // i-rows per block = 2 packed f32x2 units
#define THREADS 256
#define JSTEPS  (PNUM/THREADS) // 4

typedef unsigned long long u64f2;   // two packed fp32

__device__ int g_hist[BNUM * NBINS];

// ---- packed f32x2 primitives (sm_100+) ----
__device__ __forceinline__ u64f2 pk2(float lo, float hi) {
    u64f2 r; asm("mov.b64 %0, {%1, %2};" : "=l"(r) : "f"(lo), "f"(hi)); return r;
}
__device__ __forceinline__ void up2(u64f2 v, float& lo, float& hi) {
    asm("mov.b64 {%0, %1}, %2;" : "=f"(lo), "=f"(hi) : "l"(v));
}
__device__ __forceinline__ u64f2 f2fma(u64f2 a, u64f2 b, u64f2 c) {
    u64f2 d; asm("fma.rn.f32x2 %0, %1, %2, %3;" : "=l"(d) : "l"(a), "l"(b), "l"(c)); return d;
}
__device__ __forceinline__ u64f2 f2mul(u64f2 a, u64f2 b) {
    u64f2 d; asm("mul.rn.f32x2 %0, %1, %2;" : "=l"(d) : "l"(a), "l"(b)); return d;
}
__device__ __forceinline__ u64f2 f2add(u64f2 a, u64f2 b) {
    u64f2 d; asm("add.rn.f32x2 %0, %1, %2;" : "=l"(d) : "l"(a), "l"(b)); return d;
}
__device__ __forceinline__ u64f2 f2sub(u64f2 a, u64f2 b) {
    u64f2 d; asm("sub.rn.f32x2 %0, %1, %2;" : "=l"(d) : "l"(a), "l"(b)); return d;
}
__device__ __forceinline__ u64f2 rsq2(u64f2 v) {   // per-lane rsqrt (MUFU is scalar)
    float a, b; up2(v, a, b);
    return pk2(rsqrtf(a), rsqrtf(b));
}
// packed cross-product component: a*b - c*d
__device__ __forceinline__ u64f2 f2cr(u64f2 a, u64f2 b, u64f2 c, u64f2 d) {
    return f2sub(f2mul(a, b), f2mul(c, d));
}

// Scalar tail: atan2 fixups + binning + histogram add (one pack lane).
__device__ __forceinline__ void epilogue(float af, float pf, float r, float y,
                                         bool aygt, bool xneg, int i, int j,
                                         int* __restrict__ hist) {
    if (aygt) r = 1.57079637f - r;
    if (xneg) r = 3.14159274f - r;
    float tf = fmaf(r, copysignf(1.75070429f, y), 5.5f);  // (r/pi)*5.5+5.5, sign of y
    int ai = min((int)af, NB - 1);
    int pb = min((int)pf, NB - 1);
    int ti = min((int)tf, NB - 1);
    int idx = (ai * NB + pb) * NB + ti;
    if (idx < 0) idx += NBINS;               // JAX: single negative wrap
    if ((unsigned)idx < (unsigned)NBINS && j != i)
        atomicAdd(&hist[idx], 1);
}

__global__ __launch_bounds__(THREADS, 4) void fpfh_accum_kernel(const float* __restrict__ x) {
    __shared__ int s_hist[NBINS];

    const int b  = blockIdx.y;
    const int i0 = blockIdx.x * IPB;

    for (int t = threadIdx.x; t < NBINS; t += THREADS) s_hist[t] = 0;

    const float* __restrict__ base = x + (size_t)b * PNUM * 6;

    // i-point constants per unit u: lanes (i0+2u, i0+2u+1)
    u64f2 NPX[2], NPY[2], NPZ[2];      // -pos_i (folded into delta add)
    u64f2 NX[2],  NY[2],  NZ[2];       //  ni
    #pragma unroll
    for (int u = 0; u < 2; u++) {
        const float* p0 = base + (size_t)(i0 + 2 * u) * 6;
        const float* p1 = base + (size_t)(i0 + 2 * u + 1) * 6;
        NPX[u] = pk2(-__ldg(p0 + 0), -__ldg(p1 + 0));
        NPY[u] = pk2(-__ldg(p0 + 1), -__ldg(p1 + 1));
        NPZ[u] = pk2(-__ldg(p0 + 2), -__ldg(p1 + 2));
        NX[u]  = pk2( __ldg(p0 + 3),  __ldg(p1 + 3));
        NY[u]  = pk2( __ldg(p0 + 4),  __ldg(p1 + 4));
        NZ[u]  = pk2( __ldg(p0 + 5),  __ldg(p1 + 5));
    }
    __syncthreads();

    // packed atan polynomial constants
    const u64f2 CA1  = pk2( 0.99997726f,  0.99997726f);
    const u64f2 CA3  = pk2(-0.33262347f, -0.33262347f);
    const u64f2 CA5  = pk2( 0.19354346f,  0.19354346f);
    const u64f2 CA7  = pk2(-0.11643287f, -0.11643287f);
    const u64f2 CA9  = pk2( 0.05265332f,  0.05265332f);
    const u64f2 CA11 = pk2(-0.01172120f, -0.01172120f);
    const u64f2 K55  = pk2( 5.5f, 5.5f);

    #pragma unroll 1
    for (int jj = 0; jj < JSTEPS; jj++) {
        const int j = threadIdx.x + jj * THREADS;
        const float2* __restrict__ pj = (const float2*)(base + (size_t)j * 6);
        const float2 q0 = __ldg(pj + 0);
        const float2 q1 = __ldg(pj + 1);
        const float2 q2 = __ldg(pj + 2);
        const u64f2 JX  = pk2(q0.x, q0.x), JY  = pk2(q0.y, q0.y), JZ  = pk2(q1.x, q1.x);
        const u64f2 JNX = pk2(q1.y, q1.y), JNY = pk2(q2.x, q2.x), JNZ = pk2(q2.y, q2.y);

        #pragma unroll
        for (int u = 0; u < 2; u++) {
            // delta = pos_j - pos_i
            const u64f2 dx = f2add(JX, NPX[u]);
            const u64f2 dy = f2add(JY, NPY[u]);
            const u64f2 dz = f2add(JZ, NPZ[u]);

            const u64f2 d2   = f2fma(dx, dx, f2fma(dy, dy, f2mul(dz, dz)));
            const u64f2 pdot = f2fma(NX[u], dx, f2fma(NY[u], dy, f2mul(NZ[u], dz)));
            const u64f2 phi2 = f2mul(pdot, rsq2(d2));

            // v = cross(delta, ni)
            const u64f2 vx = f2cr(dy, NZ[u], dz, NY[u]);
            const u64f2 vy = f2cr(dz, NX[u], dx, NZ[u]);
            const u64f2 vz = f2cr(dx, NY[u], dy, NX[u]);
            const u64f2 v2 = f2fma(vx, vx, f2fma(vy, vy, f2mul(vz, vz)));
            const u64f2 adot = f2fma(vx, JNX, f2fma(vy, JNY, f2mul(vz, JNZ)));
            const u64f2 alpha2 = f2mul(adot, rsq2(v2));

            // w = cross(ni, v)
            const u64f2 wx = f2cr(NY[u], vz, NZ[u], vy);
            const u64f2 wy = f2cr(NZ[u], vx, NX[u], vz);
            const u64f2 wz = f2cr(NX[u], vy, NY[u], vx);
            const u64f2 w2   = f2fma(wx, wx, f2fma(wy, wy, f2mul(wz, wz)));
            const u64f2 wdot = f2fma(wx, JNX, f2fma(wy, JNY, f2mul(wz, JNZ)));
            const u64f2 ndot = f2fma(NX[u], JNX, f2fma(NY[u], JNY, f2mul(NZ[u], JNZ)));

            // theta = atan2(wdot, ndot*|w|)  [scale-folded form]
            float w2a, w2b; up2(w2, w2a, w2b);
            float ya,  yb;  up2(wdot, ya, yb);
            float na,  nb;  up2(ndot, na, nb);
            const float xa = na * (w2a * rsqrtf(w2a));
            const float xb = nb * (w2b * rsqrtf(w2b));

            const float axa = fabsf(xa), aya = fabsf(ya);
            const float axb = fabsf(xb), ayb = fabsf(yb);
            const bool  ga = aya > axa, gb = ayb > axb;
            const bool  sa = xa < 0.0f, sb = xb < 0.0f;
            const float ta = __fdividef(fminf(axa, aya), fmaxf(axa, aya));
            const float tb = __fdividef(fminf(axb, ayb), fmaxf(axb, ayb));

            const u64f2 T  = pk2(ta, tb);
            const u64f2 T2 = f2mul(T, T);
            u64f2 P = f2fma(T2, CA11, CA9);
            P = f2fma(T2, P, CA7);
            P = f2fma(T2, P, CA5);
            P = f2fma(T2, P, CA3);
            P = f2fma(T2, P, CA1);
            const u64f2 R = f2mul(P, T);
            float ra, rb; up2(R, ra, rb);

            const u64f2 AF = f2fma(alpha2, K55, K55);
            const u64f2 PF = f2fma(phi2,  K55, K55);
            float afa, afb; up2(AF, afa, afb);
            float pfa, pfb; up2(PF, pfa, pfb);

            epilogue(afa, pfa, ra, ya, ga, sa, i0 + 2 * u,     j, s_hist);
            epilogue(afb, pfb, rb, yb, gb, sb, i0 + 2 * u + 1, j, s_hist);
        }
    }
    __syncthreads();

    // Flush block-private histogram to the per-batch global histogram.
    int* __restrict__ gh = &g_hist[b * NBINS];
    for (int t = threadIdx.x; t < NBINS; t += THREADS) {
        int c = s_hist[t];
        if (c) atomicAdd(&gh[t], c);
    }
}

__global__ void fpfh_finalize_kernel(float* __restrict__ out) {
    int t = blockIdx.x * blockDim.x + threadIdx.x;
    if (t < BNUM * NBINS) {
        out[t] = (float)g_hist[t] / 1047552.0f;  // / (1024*1023)
        g_hist[t] = 0;                           // reset for next graph replay
    }
}

// No-op: steers ncu's fixed launch-skip so the accum kernel gets profiled.
__global__ void fpfh_pad_kernel() {}

extern "C" void kernel_launch(void* const* d_in, const int* in_sizes, int n_in,
                              void* d_out, int out_size) {
    const float* x = (const float*)d_in[0];
    float* out = (float*)d_out;

    dim3 grid(PNUM / IPB, BNUM);   // 256 x 8 = 2048 blocks
    fpfh_accum_kernel<<<grid, THREADS>>>(x);

    int total = BNUM * NBINS;
    fpfh_finalize_kernel<<<(total + 255) / 256, 256>>>(out);

    fpfh_pad_kernel<<<1, 32>>>();
}